// round 15
// baseline (speedup 1.0000x reference)
#include <cuda_runtime.h>
#include <cuda_fp16.h>
#include <stdint.h>

#define DI __device__ __forceinline__

// Problem constants
constexpr int Bb = 8, Ls = 1024, Cc = 1024, Hh = 16, Dd = 64;
constexpr int BHn = Bb * Hh;      // 128
constexpr int MT  = Bb * Ls;      // 8192 tokens
constexpr int NQKV = 3 * Cc;      // 3072

constexpr float SC2 = 0.18033688f;   // 0.125 * log2(e)

// Scratch (device globals: allocation-free per harness rules)
__device__ __half g_Q[BHn * Ls * Dd];         // 16 MB  (b,h,l,d)
__device__ __half g_K[BHn * Ls * Dd];         // 16 MB
__device__ __half g_V[BHn * Ls * Dd];         // 16 MB
__device__ __half g_Dh[BHn * Ls];             // per-(bh,j): 1/z  (= 2^d exactly)
__device__ __half g_Y[MT * Cc];               // 16 MB  (b,l,c)
__device__ __half g_Xh[MT * Cc];              // 16 MB  x as half
__device__ __half g_Wqkvh[Cc * NQKV];         // 6 MB   W_qkv as half [K][N]
__device__ __half g_Wprojh[Cc * Cc];          // 2 MB   W_proj as half [K][N]

// ---------------------------------------------------------------------------
// helpers
// ---------------------------------------------------------------------------
DI unsigned pack2(float a, float b) {
    __half2 h = __floats2half2_rn(a, b);
    return *(unsigned*)&h;
}
DI unsigned s2u(const void* p) { return (unsigned)__cvta_generic_to_shared(p); }
DI float ex2(float x) { float r; asm("ex2.approx.f32 %0, %1;" : "=f"(r) : "f"(x)); return r; }
DI unsigned hex2(unsigned x) {
    unsigned r; asm("ex2.approx.f16x2 %0, %1;" : "=r"(r) : "r"(x)); return r;
}
DI unsigned hm2(unsigned a, unsigned b) {
    unsigned r; asm("mul.rn.f16x2 %0, %1, %2;" : "=r"(r) : "r"(a), "r"(b)); return r;
}

DI void ldsm4(unsigned r[4], unsigned a) {
    asm volatile("ldmatrix.sync.aligned.m8n8.x4.shared.b16 {%0,%1,%2,%3}, [%4];"
                 : "=r"(r[0]), "=r"(r[1]), "=r"(r[2]), "=r"(r[3]) : "r"(a));
}
DI void ldsm4t(unsigned r[4], unsigned a) {
    asm volatile("ldmatrix.sync.aligned.m8n8.x4.trans.shared.b16 {%0,%1,%2,%3}, [%4];"
                 : "=r"(r[0]), "=r"(r[1]), "=r"(r[2]), "=r"(r[3]) : "r"(a));
}
DI void mma16(float c[4], const unsigned a[4], const unsigned b[2]) {
    asm volatile(
        "mma.sync.aligned.m16n8k16.row.col.f32.f16.f16.f32 "
        "{%0,%1,%2,%3}, {%4,%5,%6,%7}, {%8,%9}, {%0,%1,%2,%3};"
        : "+f"(c[0]), "+f"(c[1]), "+f"(c[2]), "+f"(c[3])
        : "r"(a[0]), "r"(a[1]), "r"(a[2]), "r"(a[3]), "r"(b[0]), "r"(b[1]));
}
DI void cp16(unsigned dst, const void* src) {
    asm volatile("cp.async.cg.shared.global [%0], [%1], 16;" :: "r"(dst), "l"(src) : "memory");
}
DI void cp_commit() { asm volatile("cp.async.commit_group;" ::: "memory"); }
template <int N> DI void cp_wait() {
    asm volatile("cp.async.wait_group %0;" :: "n"(N) : "memory");
}

// ---------------------------------------------------------------------------
// Pre-pass: fp32 -> half elementwise (x, W_qkv, W_proj)
// ---------------------------------------------------------------------------
__global__ void conv_kernel(const float* __restrict__ src, __half* __restrict__ dst) {
    size_t i = ((size_t)blockIdx.x * 256 + threadIdx.x) * 4;
    float4 v = *(const float4*)(src + i);
    *(uint2*)(dst + i) = make_uint2(pack2(v.x, v.y), pack2(v.z, v.w));
}

// ---------------------------------------------------------------------------
// Big-tile GEMM (R9 winner): C[128x256] = A[M][1024]*B[1024][NC] + bias.
// 8 warps, 64x64 warp tiles, BK=64, 3-stage cp.async ring, 1 barrier/chunk.
// ---------------------------------------------------------------------------
constexpr int STG_A_BYTES = 128 * 72 * 2;       // 18432
constexpr int STG_BYTES   = STG_A_BYTES + 64 * 264 * 2;  // 52224
constexpr int GB_SMEM = 1024 + 3 * STG_BYTES;   // 157696 B

template <int NC, int EPI>
__global__ void __launch_bounds__(256, 1)
gemm_big(const __half* __restrict__ Ah, const __half* __restrict__ Bh,
         const float* __restrict__ bias, float* __restrict__ Cout) {
    extern __shared__ char sm[];
    float* bsm = (float*)sm;
    const unsigned sbase = s2u(sm);

    const int t = threadIdx.x, lane = t & 31, wid = t >> 5;
    const int m0 = blockIdx.x * 128, n0 = blockIdx.y * 256;
    const int wm = (wid >> 2) * 64, wn = (wid & 3) * 64;
    const int lr = lane >> 2, lc = lane & 3;

    bsm[t] = bias[n0 + t];

    const int arow = t >> 3, acol = (t & 7) * 8;
    const int brow = t >> 5, bcol = (t & 31) * 8;

    const __half* agp = Ah + (size_t)(m0 + arow) * 1024 + acol;
    const __half* bgp = Bh + (size_t)brow * NC + n0 + bcol;

    const unsigned as_st = sbase + 1024 + (arow * 72 + acol) * 2;
    const unsigned bs_st = sbase + 1024 + STG_A_BYTES + (brow * 264 + bcol) * 2;

    const int qrow = (lane & 7) + ((lane >> 3) & 1) * 8;
    const int qcol = (lane >> 4) * 8;
    const unsigned a_frag = sbase + 1024 + ((wm + qrow) * 72 + qcol) * 2;
    const unsigned b_frag = sbase + 1024 + STG_A_BYTES + (qrow * 264 + wn + qcol) * 2;

    float acc[4][8][4];
#pragma unroll
    for (int i = 0; i < 4; i++)
#pragma unroll
        for (int j = 0; j < 8; j++)
#pragma unroll
            for (int q = 0; q < 4; q++) acc[i][j][q] = 0.f;

#define ISSUE(kt)                                                          \
    do {                                                                   \
        const unsigned so_ = ((kt) % 3) * STG_BYTES;                       \
        const __half* ag_ = agp + (size_t)(kt) * 64;                       \
        _Pragma("unroll")                                                  \
        for (int i_ = 0; i_ < 4; i_++)                                     \
            cp16(as_st + so_ + i_ * 32 * 144, ag_ + (size_t)(32 * i_) * 1024); \
        const __half* bg_ = bgp + (size_t)(kt) * 64 * NC;                  \
        _Pragma("unroll")                                                  \
        for (int i_ = 0; i_ < 8; i_++)                                     \
            cp16(bs_st + so_ + i_ * 8 * 528, bg_ + (size_t)(8 * i_) * NC); \
        cp_commit();                                                       \
    } while (0)

    ISSUE(0); ISSUE(1);

#pragma unroll 1
    for (int kt = 0; kt < 16; kt++) {
        cp_wait<1>();
        __syncthreads();
        if (kt + 2 < 16) ISSUE(kt + 2);
        const unsigned so = (kt % 3) * STG_BYTES;
#pragma unroll
        for (int ks = 0; ks < 4; ks++) {
            unsigned af[4][4], bq[4][4];
#pragma unroll
            for (int im = 0; im < 4; im++)
                ldsm4(af[im], a_frag + so + im * 16 * 144 + ks * 32);
#pragma unroll
            for (int np = 0; np < 4; np++)
                ldsm4t(bq[np], b_frag + so + ks * 16 * 528 + np * 32);
#pragma unroll
            for (int im = 0; im < 4; im++)
#pragma unroll
                for (int np = 0; np < 4; np++) {
                    mma16(acc[im][np * 2],     af[im], &bq[np][0]);
                    mma16(acc[im][np * 2 + 1], af[im], &bq[np][2]);
                }
        }
    }
#undef ISSUE

#pragma unroll
    for (int im = 0; im < 4; im++) {
#pragma unroll
        for (int j = 0; j < 8; j++) {
            int r0 = m0 + wm + im * 16 + lr;
            int c0 = wn + j * 8 + lc * 2;
            float bz0 = bsm[c0], bz1 = bsm[c0 + 1];
            int gc = n0 + c0;
#pragma unroll
            for (int h2 = 0; h2 < 2; h2++) {
                int r = r0 + h2 * 8;
                float v0 = acc[im][j][h2 * 2 + 0] + bz0;
                float v1 = acc[im][j][h2 * 2 + 1] + bz1;
                if (EPI == 0) {
                    *(float2*)&Cout[(size_t)r * NC + gc] = make_float2(v0, v1);
                } else {
                    int sec = gc >> 10, w = gc & 1023;
                    int hh = w >> 6, dd = w & 63;
                    int bi = r >> 10, li = r & 1023;
                    __half* dst = (sec == 0) ? g_Q : (sec == 1) ? g_K : g_V;
                    *(__half2*)&dst[(((size_t)(bi * Hh + hh)) * Ls + li) * Dd + dd] =
                        __floats2half2_rn(v0, v1);
                }
            }
        }
    }
}

// ---------------------------------------------------------------------------
// Pass 1: per-key-column stats (m=0 softmax), Q tiles via 2-stage cp.async.
// Output: g_Dh[j] = half(1/z)  (= 2^{-log2 z} exactly).
// smem halfs: K[128*72] | Qstage0[128*72] | Qstage1[128*72]   (55296 B)
// ---------------------------------------------------------------------------
constexpr int ST_QOFF = 128 * 72 * 2;
constexpr int ST_QSTG = 128 * 72 * 2;
constexpr int ST_SMEM = ST_QOFF + 2 * ST_QSTG;  // 55296 B

__global__ void __launch_bounds__(256, 2) stats_kernel2() {
    extern __shared__ __half smh[];
    const unsigned sbase = s2u(smh);

    const int jt = blockIdx.x, bh = blockIdx.y;
    const int t = threadIdx.x;
    const int lane = t & 31, wid = t >> 5;
    const int lr = lane >> 2, lc = lane & 3;
    const int wm = wid * 16;
    const int tr = t >> 3, tc = (t & 7) * 8;

    const int srow = (lane & 7) + ((lane >> 4) << 3);
    const int scol = ((lane >> 3) & 1) * 8;
    const unsigned qb0 = sbase + ST_QOFF + (srow * 72 + scol) * 2;

    const __half* Kp = g_K + ((size_t)bh * Ls + jt * 128) * Dd;
    const __half* Qp = g_Q + (size_t)bh * Ls * Dd;

    const unsigned k_st = sbase + (tr * 72 + tc) * 2;
    const unsigned q_st = sbase + ST_QOFF + (tr * 72 + tc) * 2;

    {
#pragma unroll
        for (int i = 0; i < 4; i++)
            cp16(k_st + i * 32 * 144, Kp + (size_t)(tr + 32 * i) * Dd + tc);
#pragma unroll
        for (int i = 0; i < 4; i++)
            cp16(q_st + i * 32 * 144,
                 Qp + (size_t)(jt * 128 + tr + 32 * i) * Dd + tc);
        cp_commit();
    }
    if (jt + 1 < 8) {
#pragma unroll
        for (int i = 0; i < 4; i++)
            cp16(q_st + ST_QSTG + i * 32 * 144,
                 Qp + (size_t)((jt + 1) * 128 + tr + 32 * i) * Dd + tc);
        cp_commit();
    }

    unsigned af[4][4];
    float z0 = 0.f, z1 = 0.f;
    const int j0 = jt * 128 + wm + lr;
    const int j1 = j0 + 8;
    const int M = 8 - jt;

#pragma unroll 1
    for (int m = 0; m < M; m++) {
        const int it = jt + m;
        const int s = m & 1;
        if (m == M - 1) cp_wait<0>(); else cp_wait<1>();
        __syncthreads();
        if (m == 0) {
#pragma unroll
            for (int ks = 0; ks < 4; ks++) {
                int k = ks * 16 + lc * 2;
                af[ks][0] = *(unsigned*)&smh[(wm + lr) * 72 + k];
                af[ks][1] = *(unsigned*)&smh[(wm + lr + 8) * 72 + k];
                af[ks][2] = *(unsigned*)&smh[(wm + lr) * 72 + k + 8];
                af[ks][3] = *(unsigned*)&smh[(wm + lr + 8) * 72 + k + 8];
            }
        }
        const unsigned qso = (unsigned)s * ST_QSTG;
        const bool diag = (it == jt);
#pragma unroll
        for (int ntp = 0; ntp < 8; ntp++) {
            float acc0[4] = {0.f, 0.f, 0.f, 0.f};
            float acc1[4] = {0.f, 0.f, 0.f, 0.f};
#pragma unroll
            for (int ks = 0; ks < 4; ks++) {
                unsigned bq[4];
                ldsm4(bq, qb0 + qso + (ntp * 16 * 72 + ks * 16) * 2);
                mma16(acc0, af[ks], &bq[0]);
                mma16(acc1, af[ks], &bq[2]);
            }
            int i0 = it * 128 + ntp * 16 + lc * 2;
            int i1 = i0 + 8;
            float e00 = (!diag || i0 >= j0)     ? ex2(acc0[0] * SC2) : 0.f;
            float e01 = (!diag || i0 + 1 >= j0) ? ex2(acc0[1] * SC2) : 0.f;
            float e02 = (!diag || i1 >= j0)     ? ex2(acc1[0] * SC2) : 0.f;
            float e03 = (!diag || i1 + 1 >= j0) ? ex2(acc1[1] * SC2) : 0.f;
            float e10 = (!diag || i0 >= j1)     ? ex2(acc0[2] * SC2) : 0.f;
            float e11 = (!diag || i0 + 1 >= j1) ? ex2(acc0[3] * SC2) : 0.f;
            float e12 = (!diag || i1 >= j1)     ? ex2(acc1[2] * SC2) : 0.f;
            float e13 = (!diag || i1 + 1 >= j1) ? ex2(acc1[3] * SC2) : 0.f;
            z0 += (e00 + e01) + (e02 + e03);
            z1 += (e10 + e11) + (e12 + e13);
        }
        __syncthreads();
        if (it + 2 < 8) {
#pragma unroll
            for (int i = 0; i < 4; i++)
                cp16(q_st + (unsigned)s * ST_QSTG + i * 32 * 144,
                     Qp + (size_t)((it + 2) * 128 + tr + 32 * i) * Dd + tc);
            cp_commit();
        }
    }

#pragma unroll
    for (int off = 1; off <= 2; off <<= 1) {
        z0 += __shfl_xor_sync(0xFFFFFFFFu, z0, off);
        z1 += __shfl_xor_sync(0xFFFFFFFFu, z1, off);
    }
    if (lc == 0) {
        g_Dh[bh * Ls + j0] = __float2half(1.f / z0);
        g_Dh[bh * Ls + j1] = __float2half(1.f / z1);
    }
}

// ---------------------------------------------------------------------------
// Pass 2: fused attention, register-direct GEMM1->GEMM2, K/V/p via 2-stage
// cp.async.  Weights in packed-half: w = (ex2.f16x2(s*SC2)) * (1/z as half).
// smem: stage s: K[128*72] V[128*72] (halfs); then p[2][128] half.
// ---------------------------------------------------------------------------
constexpr int ATT_V_OFF = 128 * 72 * 2;          // V offset within stage (bytes)
constexpr int ATT_STG_B = 2 * 128 * 72 * 2;      // 36864 B per stage
constexpr int ATT_P_OFF = 2 * ATT_STG_B;         // 73728
constexpr int P2_SMEM = ATT_P_OFF + 2 * 256;     // 74240 B

__global__ void __launch_bounds__(256, 2) attn_kernel2() {
    extern __shared__ __half smh[];
    const unsigned sbase = s2u(smh);

    const int it = 7 - blockIdx.x;
    const int bh = blockIdx.y;
    const int b = bh >> 4, h = bh & 15;
    const int t = threadIdx.x;
    const int lane = t & 31, wid = t >> 5;
    const int lr = lane >> 2, lc = lane & 3;
    const int wm = wid * 16;
    const int tr = t >> 3, tc = (t & 7) * 8;

    const __half* Qp = g_Q + ((size_t)bh * Ls + it * 128) * Dd;
    const __half* Kp = g_K + (size_t)bh * Ls * Dd;
    const __half* Vp = g_V + (size_t)bh * Ls * Dd;

    const int vrow = (lane & 7) + ((lane >> 3) & 1) * 8;
    const int vcol = (lane >> 4) * 8;
    const unsigned Vb0 = sbase + ATT_V_OFF + (vrow * 72 + vcol) * 2;
    const int srow = (lane & 7) + ((lane >> 4) << 3);
    const int scol = ((lane >> 3) & 1) * 8;
    const unsigned kb0 = sbase + (srow * 72 + scol) * 2;

    const unsigned k_st = sbase + (tr * 72 + tc) * 2;
    const unsigned v_st = k_st + ATT_V_OFF;

    const unsigned SC2H2 = pack2(SC2, SC2);

    // prologue: stage Q into stage-0 K area (plain stores), read fragments
#pragma unroll
    for (int i = 0; i < 4; i++) {
        int r = tr + 32 * i;
        *(uint4*)&smh[(size_t)r * 72 + tc] = *(const uint4*)(Qp + (size_t)r * Dd + tc);
    }
    __syncthreads();
    unsigned qf[4][4];
#pragma unroll
    for (int ks = 0; ks < 4; ks++) {
        int k = ks * 16 + lc * 2;
        qf[ks][0] = *(unsigned*)&smh[(wm + lr) * 72 + k];
        qf[ks][1] = *(unsigned*)&smh[(wm + lr + 8) * 72 + k];
        qf[ks][2] = *(unsigned*)&smh[(wm + lr) * 72 + k + 8];
        qf[ks][3] = *(unsigned*)&smh[(wm + lr + 8) * 72 + k + 8];
    }
    __syncthreads();

#define AISSUE(kt)                                                         \
    do {                                                                   \
        const unsigned so_ = (unsigned)((kt) & 1) * ATT_STG_B;             \
        const __half* kg_ = Kp + (size_t)((kt) * 128 + tr) * Dd + tc;      \
        const __half* vg_ = Vp + (size_t)((kt) * 128 + tr) * Dd + tc;      \
        _Pragma("unroll")                                                  \
        for (int i_ = 0; i_ < 4; i_++) {                                   \
            cp16(k_st + so_ + i_ * 32 * 144, kg_ + (size_t)(32 * i_) * Dd);\
            cp16(v_st + so_ + i_ * 32 * 144, vg_ + (size_t)(32 * i_) * Dd);\
        }                                                                  \
        if (t < 16)                                                        \
            cp16(sbase + ATT_P_OFF + ((kt) & 1) * 256 + t * 16,            \
                 g_Dh + (size_t)bh * Ls + (kt) * 128 + t * 8);             \
        cp_commit();                                                       \
    } while (0)

    AISSUE(0);
    if (it >= 1) AISSUE(1);

    float yacc[8][4];
#pragma unroll
    for (int i = 0; i < 8; i++)
#pragma unroll
        for (int q = 0; q < 4; q++) yacc[i][q] = 0.f;

    const int i0r = it * 128 + wm + lr;
    const int i1r = i0r + 8;

#pragma unroll 1
    for (int kt = 0; kt <= it; kt++) {
        const int s = kt & 1;
        const unsigned so = (unsigned)s * ATT_STG_B;
        if (kt == it) cp_wait<0>(); else cp_wait<1>();
        __syncthreads();
        const __half* psm = (const __half*)((const char*)smh + ATT_P_OFF + s * 256);

        const bool diag = (kt == it);
#pragma unroll
        for (int ntp = 0; ntp < 8; ntp++) {
            float acc0[4] = {0.f, 0.f, 0.f, 0.f};
            float acc1[4] = {0.f, 0.f, 0.f, 0.f};
#pragma unroll
            for (int ks = 0; ks < 4; ks++) {
                unsigned bq[4];
                ldsm4(bq, kb0 + so + (ntp * 16 * 72 + ks * 16) * 2);
                mma16(acc0, qf[ks], &bq[0]);
                mma16(acc1, qf[ks], &bq[2]);
            }
            // hoist V fragments: overlap LDSM with the exp chain below
            unsigned bt[4][4];
#pragma unroll
            for (int dtp = 0; dtp < 4; dtp++)
                ldsm4t(bt[dtp], Vb0 + so + (ntp * 16 * 72 + dtp * 16) * 2);

            int jl0 = ntp * 16 + lc * 2;
            int jl1 = jl0 + 8;
            if (diag) {
                int jg0 = kt * 128 + jl0, jg1 = kt * 128 + jl1;
                if (i0r < jg0)     acc0[0] = -1e5f;
                if (i0r < jg0 + 1) acc0[1] = -1e5f;
                if (i1r < jg0)     acc0[2] = -1e5f;
                if (i1r < jg0 + 1) acc0[3] = -1e5f;
                if (i0r < jg1)     acc1[0] = -1e5f;
                if (i0r < jg1 + 1) acc1[1] = -1e5f;
                if (i1r < jg1)     acc1[2] = -1e5f;
                if (i1r < jg1 + 1) acc1[3] = -1e5f;
            }
            const unsigned pp01 = *(const unsigned*)&psm[jl0];
            const unsigned pp23 = *(const unsigned*)&psm[jl1];
            unsigned aw[4];
            aw[0] = hm2(hex2(hm2(pack2(acc0[0], acc0[1]), SC2H2)), pp01);
            aw[1] = hm2(hex2(hm2(pack2(acc0[2], acc0[3]), SC2H2)), pp01);
            aw[2] = hm2(hex2(hm2(pack2(acc1[0], acc1[1]), SC2H2)), pp23);
            aw[3] = hm2(hex2(hm2(pack2(acc1[2], acc1[3]), SC2H2)), pp23);
#pragma unroll
            for (int dtp = 0; dtp < 4; dtp++) {
                mma16(yacc[dtp * 2],     aw, &bt[dtp][0]);
                mma16(yacc[dtp * 2 + 1], aw, &bt[dtp][2]);
            }
        }
        __syncthreads();
        if (kt + 2 <= it) AISSUE(kt + 2);
    }
#undef AISSUE

#pragma unroll
    for (int dt = 0; dt < 8; dt++) {
        int d0 = dt * 8 + lc * 2;
        *(__half2*)&g_Y[((size_t)(b * Ls + i0r)) * Cc + h * Dd + d0] =
            __floats2half2_rn(yacc[dt][0], yacc[dt][1]);
        *(__half2*)&g_Y[((size_t)(b * Ls + i1r)) * Cc + h * Dd + d0] =
            __floats2half2_rn(yacc[dt][2], yacc[dt][3]);
    }
}

// ---------------------------------------------------------------------------
// Launch
// ---------------------------------------------------------------------------
extern "C" void kernel_launch(void* const* d_in, const int* in_sizes, int n_in,
                              void* d_out, int out_size) {
    const float* x     = (const float*)d_in[0];
    const float* Wqkv  = (const float*)d_in[1];
    const float* bqkv  = (const float*)d_in[2];
    const float* Wproj = (const float*)d_in[3];
    const float* bproj = (const float*)d_in[4];
    float* out = (float*)d_out;

    __half *xh, *wq, *wp, *yh;
    cudaGetSymbolAddress((void**)&xh, g_Xh);
    cudaGetSymbolAddress((void**)&wq, g_Wqkvh);
    cudaGetSymbolAddress((void**)&wp, g_Wprojh);
    cudaGetSymbolAddress((void**)&yh, g_Y);

    (void)cudaFuncSetAttribute(gemm_big<NQKV, 1>,
                               cudaFuncAttributeMaxDynamicSharedMemorySize, GB_SMEM);
    (void)cudaFuncSetAttribute(gemm_big<Cc, 0>,
                               cudaFuncAttributeMaxDynamicSharedMemorySize, GB_SMEM);
    (void)cudaFuncSetAttribute(stats_kernel2,
                               cudaFuncAttributeMaxDynamicSharedMemorySize, ST_SMEM);
    (void)cudaFuncSetAttribute(attn_kernel2,
                               cudaFuncAttributeMaxDynamicSharedMemorySize, P2_SMEM);

    // pre-passes: fp32 -> half
    conv_kernel<<<MT * Cc / 1024, 256>>>(x, xh);
    conv_kernel<<<Cc * NQKV / 1024, 256>>>(Wqkv, wq);
    conv_kernel<<<Cc * Cc / 1024, 256>>>(Wproj, wp);

    // QKV projection, scatter half into per-head Q/K/V
    gemm_big<NQKV, 1><<<dim3(MT / 128, NQKV / 256), 256, GB_SMEM>>>(xh, wq, bqkv, nullptr);
    // softmax stats + fused attention
    stats_kernel2<<<dim3(8, BHn), 256, ST_SMEM>>>();
    attn_kernel2<<<dim3(8, BHn), 256, P2_SMEM>>>();
    // output projection (fp32 out)
    gemm_big<Cc, 0><<<dim3(MT / 128, Cc / 256), 256, GB_SMEM>>>(yh, wp, bproj, out);
}

// round 16
// speedup vs baseline: 1.0100x; 1.0100x over previous
#include <cuda_runtime.h>
#include <cuda_fp16.h>
#include <stdint.h>

#define DI __device__ __forceinline__

// Problem constants
constexpr int Bb = 8, Ls = 1024, Cc = 1024, Hh = 16, Dd = 64;
constexpr int BHn = Bb * Hh;      // 128
constexpr int MT  = Bb * Ls;      // 8192 tokens
constexpr int NQKV = 3 * Cc;      // 3072

constexpr float SC2 = 0.18033688f;   // 0.125 * log2(e)

// Scratch (device globals: allocation-free per harness rules)
__device__ __half g_Q[BHn * Ls * Dd];         // 16 MB  (b,h,l,d)
__device__ __half g_K[BHn * Ls * Dd];         // 16 MB
__device__ __half g_V[BHn * Ls * Dd];         // 16 MB
__device__ float  g_D[BHn * Ls];              // per-(bh,j): -log2(sum exp)
__device__ __half g_Y[MT * Cc];               // 16 MB  (b,l,c)
__device__ __half g_Xh[MT * Cc];              // 16 MB  x as half
__device__ __half g_Wqkvh[Cc * NQKV];         // 6 MB   W_qkv as half [K][N]
__device__ __half g_Wprojh[Cc * Cc];          // 2 MB   W_proj as half [K][N]

// ---------------------------------------------------------------------------
// helpers
// ---------------------------------------------------------------------------
DI unsigned pack2(float a, float b) {
    __half2 h = __floats2half2_rn(a, b);
    return *(unsigned*)&h;
}
DI unsigned s2u(const void* p) { return (unsigned)__cvta_generic_to_shared(p); }
DI float ex2(float x) { float r; asm("ex2.approx.f32 %0, %1;" : "=f"(r) : "f"(x)); return r; }
DI float lg2(float x) { float r; asm("lg2.approx.f32 %0, %1;" : "=f"(r) : "f"(x)); return r; }

DI void ldsm4(unsigned r[4], unsigned a) {
    asm volatile("ldmatrix.sync.aligned.m8n8.x4.shared.b16 {%0,%1,%2,%3}, [%4];"
                 : "=r"(r[0]), "=r"(r[1]), "=r"(r[2]), "=r"(r[3]) : "r"(a));
}
DI void ldsm4t(unsigned r[4], unsigned a) {
    asm volatile("ldmatrix.sync.aligned.m8n8.x4.trans.shared.b16 {%0,%1,%2,%3}, [%4];"
                 : "=r"(r[0]), "=r"(r[1]), "=r"(r[2]), "=r"(r[3]) : "r"(a));
}
DI void mma16(float c[4], const unsigned a[4], const unsigned b[2]) {
    asm volatile(
        "mma.sync.aligned.m16n8k16.row.col.f32.f16.f16.f32 "
        "{%0,%1,%2,%3}, {%4,%5,%6,%7}, {%8,%9}, {%0,%1,%2,%3};"
        : "+f"(c[0]), "+f"(c[1]), "+f"(c[2]), "+f"(c[3])
        : "r"(a[0]), "r"(a[1]), "r"(a[2]), "r"(a[3]), "r"(b[0]), "r"(b[1]));
}
DI void cp16(unsigned dst, const void* src) {
    asm volatile("cp.async.cg.shared.global [%0], [%1], 16;" :: "r"(dst), "l"(src) : "memory");
}
DI void cp_commit() { asm volatile("cp.async.commit_group;" ::: "memory"); }
template <int N> DI void cp_wait() {
    asm volatile("cp.async.wait_group %0;" :: "n"(N) : "memory");
}

// ---------------------------------------------------------------------------
// Pre-pass: fp32 -> half for x, W_qkv, W_proj in ONE launch.
// Block ranges: [0,8192) x | [8192,11264) W_qkv | [11264,12288) W_proj
// ---------------------------------------------------------------------------
__global__ void conv_all_kernel(const float* __restrict__ x,
                                const float* __restrict__ wq,
                                const float* __restrict__ wp) {
    int bid = blockIdx.x;
    const float* src;
    __half* dst;
    size_t base;
    if (bid < 8192)       { src = x;  dst = g_Xh;    base = (size_t)bid; }
    else if (bid < 11264) { src = wq; dst = g_Wqkvh; base = (size_t)(bid - 8192); }
    else                  { src = wp; dst = g_Wprojh; base = (size_t)(bid - 11264); }
    size_t i = (base * 256 + threadIdx.x) * 4;
    float4 v = *(const float4*)(src + i);
    *(uint2*)(dst + i) = make_uint2(pack2(v.x, v.y), pack2(v.z, v.w));
}

// ---------------------------------------------------------------------------
// Big-tile GEMM (R9 winner): C[128x256] = A[M][1024]*B[1024][NC] + bias.
// 8 warps, 64x64 warp tiles, BK=64, 3-stage cp.async ring, 1 barrier/chunk.
// ---------------------------------------------------------------------------
constexpr int STG_A_BYTES = 128 * 72 * 2;       // 18432
constexpr int STG_BYTES   = STG_A_BYTES + 64 * 264 * 2;  // 52224
constexpr int GB_SMEM = 1024 + 3 * STG_BYTES;   // 157696 B

template <int NC, int EPI>
__global__ void __launch_bounds__(256, 1)
gemm_big(const __half* __restrict__ Ah, const __half* __restrict__ Bh,
         const float* __restrict__ bias, float* __restrict__ Cout) {
    extern __shared__ char sm[];
    float* bsm = (float*)sm;
    const unsigned sbase = s2u(sm);

    const int t = threadIdx.x, lane = t & 31, wid = t >> 5;
    const int m0 = blockIdx.x * 128, n0 = blockIdx.y * 256;
    const int wm = (wid >> 2) * 64, wn = (wid & 3) * 64;
    const int lr = lane >> 2, lc = lane & 3;

    bsm[t] = bias[n0 + t];

    const int arow = t >> 3, acol = (t & 7) * 8;
    const int brow = t >> 5, bcol = (t & 31) * 8;

    const __half* agp = Ah + (size_t)(m0 + arow) * 1024 + acol;
    const __half* bgp = Bh + (size_t)brow * NC + n0 + bcol;

    const unsigned as_st = sbase + 1024 + (arow * 72 + acol) * 2;
    const unsigned bs_st = sbase + 1024 + STG_A_BYTES + (brow * 264 + bcol) * 2;

    const int qrow = (lane & 7) + ((lane >> 3) & 1) * 8;
    const int qcol = (lane >> 4) * 8;
    const unsigned a_frag = sbase + 1024 + ((wm + qrow) * 72 + qcol) * 2;
    const unsigned b_frag = sbase + 1024 + STG_A_BYTES + (qrow * 264 + wn + qcol) * 2;

    float acc[4][8][4];
#pragma unroll
    for (int i = 0; i < 4; i++)
#pragma unroll
        for (int j = 0; j < 8; j++)
#pragma unroll
            for (int q = 0; q < 4; q++) acc[i][j][q] = 0.f;

#define ISSUE(kt)                                                          \
    do {                                                                   \
        const unsigned so_ = ((kt) % 3) * STG_BYTES;                       \
        const __half* ag_ = agp + (size_t)(kt) * 64;                       \
        _Pragma("unroll")                                                  \
        for (int i_ = 0; i_ < 4; i_++)                                     \
            cp16(as_st + so_ + i_ * 32 * 144, ag_ + (size_t)(32 * i_) * 1024); \
        const __half* bg_ = bgp + (size_t)(kt) * 64 * NC;                  \
        _Pragma("unroll")                                                  \
        for (int i_ = 0; i_ < 8; i_++)                                     \
            cp16(bs_st + so_ + i_ * 8 * 528, bg_ + (size_t)(8 * i_) * NC); \
        cp_commit();                                                       \
    } while (0)

    ISSUE(0); ISSUE(1);

#pragma unroll 1
    for (int kt = 0; kt < 16; kt++) {
        cp_wait<1>();
        __syncthreads();
        if (kt + 2 < 16) ISSUE(kt + 2);
        const unsigned so = (kt % 3) * STG_BYTES;
#pragma unroll
        for (int ks = 0; ks < 4; ks++) {
            unsigned af[4][4], bq[4][4];
#pragma unroll
            for (int im = 0; im < 4; im++)
                ldsm4(af[im], a_frag + so + im * 16 * 144 + ks * 32);
#pragma unroll
            for (int np = 0; np < 4; np++)
                ldsm4t(bq[np], b_frag + so + ks * 16 * 528 + np * 32);
#pragma unroll
            for (int im = 0; im < 4; im++)
#pragma unroll
                for (int np = 0; np < 4; np++) {
                    mma16(acc[im][np * 2],     af[im], &bq[np][0]);
                    mma16(acc[im][np * 2 + 1], af[im], &bq[np][2]);
                }
        }
    }
#undef ISSUE

#pragma unroll
    for (int im = 0; im < 4; im++) {
#pragma unroll
        for (int j = 0; j < 8; j++) {
            int r0 = m0 + wm + im * 16 + lr;
            int c0 = wn + j * 8 + lc * 2;
            float bz0 = bsm[c0], bz1 = bsm[c0 + 1];
            int gc = n0 + c0;
#pragma unroll
            for (int h2 = 0; h2 < 2; h2++) {
                int r = r0 + h2 * 8;
                float v0 = acc[im][j][h2 * 2 + 0] + bz0;
                float v1 = acc[im][j][h2 * 2 + 1] + bz1;
                if (EPI == 0) {
                    *(float2*)&Cout[(size_t)r * NC + gc] = make_float2(v0, v1);
                } else {
                    int sec = gc >> 10, w = gc & 1023;
                    int hh = w >> 6, dd = w & 63;
                    int bi = r >> 10, li = r & 1023;
                    __half* dst = (sec == 0) ? g_Q : (sec == 1) ? g_K : g_V;
                    *(__half2*)&dst[(((size_t)(bi * Hh + hh)) * Ls + li) * Dd + dd] =
                        __floats2half2_rn(v0, v1);
                }
            }
        }
    }
}

// ---------------------------------------------------------------------------
// Pass 1: per-key-column stats (m=0 softmax), Q tiles via 2-stage cp.async.
// Output: g_D[j] = -log2(sum_{i>=j} exp2(s_ij*SC2)).
// smem halfs: K[128*72] | Qstage0[128*72] | Qstage1[128*72]   (55296 B)
// ---------------------------------------------------------------------------
constexpr int ST_QOFF = 128 * 72 * 2;
constexpr int ST_QSTG = 128 * 72 * 2;
constexpr int ST_SMEM = ST_QOFF + 2 * ST_QSTG;  // 55296 B

__global__ void __launch_bounds__(256, 2) stats_kernel2() {
    extern __shared__ __half smh[];
    const unsigned sbase = s2u(smh);

    const int jt = blockIdx.x, bh = blockIdx.y;
    const int t = threadIdx.x;
    const int lane = t & 31, wid = t >> 5;
    const int lr = lane >> 2, lc = lane & 3;
    const int wm = wid * 16;
    const int tr = t >> 3, tc = (t & 7) * 8;

    const int srow = (lane & 7) + ((lane >> 4) << 3);
    const int scol = ((lane >> 3) & 1) * 8;
    const unsigned qb0 = sbase + ST_QOFF + (srow * 72 + scol) * 2;

    const __half* Kp = g_K + ((size_t)bh * Ls + jt * 128) * Dd;
    const __half* Qp = g_Q + (size_t)bh * Ls * Dd;

    const unsigned k_st = sbase + (tr * 72 + tc) * 2;
    const unsigned q_st = sbase + ST_QOFF + (tr * 72 + tc) * 2;

    {
#pragma unroll
        for (int i = 0; i < 4; i++)
            cp16(k_st + i * 32 * 144, Kp + (size_t)(tr + 32 * i) * Dd + tc);
#pragma unroll
        for (int i = 0; i < 4; i++)
            cp16(q_st + i * 32 * 144,
                 Qp + (size_t)(jt * 128 + tr + 32 * i) * Dd + tc);
        cp_commit();
    }
    if (jt + 1 < 8) {
#pragma unroll
        for (int i = 0; i < 4; i++)
            cp16(q_st + ST_QSTG + i * 32 * 144,
                 Qp + (size_t)((jt + 1) * 128 + tr + 32 * i) * Dd + tc);
        cp_commit();
    }

    unsigned af[4][4];
    float z0 = 0.f, z1 = 0.f;
    const int j0 = jt * 128 + wm + lr;
    const int j1 = j0 + 8;
    const int M = 8 - jt;

#pragma unroll 1
    for (int m = 0; m < M; m++) {
        const int it = jt + m;
        const int s = m & 1;
        if (m == M - 1) cp_wait<0>(); else cp_wait<1>();
        __syncthreads();
        if (m == 0) {
#pragma unroll
            for (int ks = 0; ks < 4; ks++) {
                int k = ks * 16 + lc * 2;
                af[ks][0] = *(unsigned*)&smh[(wm + lr) * 72 + k];
                af[ks][1] = *(unsigned*)&smh[(wm + lr + 8) * 72 + k];
                af[ks][2] = *(unsigned*)&smh[(wm + lr) * 72 + k + 8];
                af[ks][3] = *(unsigned*)&smh[(wm + lr + 8) * 72 + k + 8];
            }
        }
        const unsigned qso = (unsigned)s * ST_QSTG;
        const bool diag = (it == jt);
#pragma unroll
        for (int ntp = 0; ntp < 8; ntp++) {
            float acc0[4] = {0.f, 0.f, 0.f, 0.f};
            float acc1[4] = {0.f, 0.f, 0.f, 0.f};
#pragma unroll
            for (int ks = 0; ks < 4; ks++) {
                unsigned bq[4];
                ldsm4(bq, qb0 + qso + (ntp * 16 * 72 + ks * 16) * 2);
                mma16(acc0, af[ks], &bq[0]);
                mma16(acc1, af[ks], &bq[2]);
            }
            int i0 = it * 128 + ntp * 16 + lc * 2;
            int i1 = i0 + 8;
            float e00 = (!diag || i0 >= j0)     ? ex2(acc0[0] * SC2) : 0.f;
            float e01 = (!diag || i0 + 1 >= j0) ? ex2(acc0[1] * SC2) : 0.f;
            float e02 = (!diag || i1 >= j0)     ? ex2(acc1[0] * SC2) : 0.f;
            float e03 = (!diag || i1 + 1 >= j0) ? ex2(acc1[1] * SC2) : 0.f;
            float e10 = (!diag || i0 >= j1)     ? ex2(acc0[2] * SC2) : 0.f;
            float e11 = (!diag || i0 + 1 >= j1) ? ex2(acc0[3] * SC2) : 0.f;
            float e12 = (!diag || i1 >= j1)     ? ex2(acc1[2] * SC2) : 0.f;
            float e13 = (!diag || i1 + 1 >= j1) ? ex2(acc1[3] * SC2) : 0.f;
            z0 += (e00 + e01) + (e02 + e03);
            z1 += (e10 + e11) + (e12 + e13);
        }
        __syncthreads();
        if (it + 2 < 8) {
#pragma unroll
            for (int i = 0; i < 4; i++)
                cp16(q_st + (unsigned)s * ST_QSTG + i * 32 * 144,
                     Qp + (size_t)((it + 2) * 128 + tr + 32 * i) * Dd + tc);
            cp_commit();
        }
    }

#pragma unroll
    for (int off = 1; off <= 2; off <<= 1) {
        z0 += __shfl_xor_sync(0xFFFFFFFFu, z0, off);
        z1 += __shfl_xor_sync(0xFFFFFFFFu, z1, off);
    }
    if (lc == 0) {
        g_D[bh * Ls + j0] = -lg2(z0);
        g_D[bh * Ls + j1] = -lg2(z1);
    }
}

// ---------------------------------------------------------------------------
// Pass 2: fused attention, register-direct GEMM1->GEMM2, K/V/d via 3-stage
// cp.async ring (ONE barrier per kt).
// smem: stage s (x3): K[128*72] V[128*72] halfs; then d[3][128] fp32.
// ---------------------------------------------------------------------------
constexpr int ATT_V_OFF = 128 * 72 * 2;          // V offset within stage (bytes)
constexpr int ATT_STG_B = 2 * 128 * 72 * 2;      // 36864 B per stage
constexpr int ATT_D_OFF = 3 * ATT_STG_B;         // 110592
constexpr int P2_SMEM = ATT_D_OFF + 3 * 512;     // 112128 B

__global__ void __launch_bounds__(256, 2) attn_kernel2() {
    extern __shared__ __half smh[];
    const unsigned sbase = s2u(smh);

    const int it = 7 - blockIdx.x;
    const int bh = blockIdx.y;
    const int b = bh >> 4, h = bh & 15;
    const int t = threadIdx.x;
    const int lane = t & 31, wid = t >> 5;
    const int lr = lane >> 2, lc = lane & 3;
    const int wm = wid * 16;
    const int tr = t >> 3, tc = (t & 7) * 8;

    const __half* Qp = g_Q + ((size_t)bh * Ls + it * 128) * Dd;
    const __half* Kp = g_K + (size_t)bh * Ls * Dd;
    const __half* Vp = g_V + (size_t)bh * Ls * Dd;

    const int vrow = (lane & 7) + ((lane >> 3) & 1) * 8;
    const int vcol = (lane >> 4) * 8;
    const unsigned Vb0 = sbase + ATT_V_OFF + (vrow * 72 + vcol) * 2;
    const int srow = (lane & 7) + ((lane >> 4) << 3);
    const int scol = ((lane >> 3) & 1) * 8;
    const unsigned kb0 = sbase + (srow * 72 + scol) * 2;

    const unsigned k_st = sbase + (tr * 72 + tc) * 2;
    const unsigned v_st = k_st + ATT_V_OFF;

    // prologue: stage Q into stage-0 K area (plain stores), read fragments
#pragma unroll
    for (int i = 0; i < 4; i++) {
        int r = tr + 32 * i;
        *(uint4*)&smh[(size_t)r * 72 + tc] = *(const uint4*)(Qp + (size_t)r * Dd + tc);
    }
    __syncthreads();
    unsigned qf[4][4];
#pragma unroll
    for (int ks = 0; ks < 4; ks++) {
        int k = ks * 16 + lc * 2;
        qf[ks][0] = *(unsigned*)&smh[(wm + lr) * 72 + k];
        qf[ks][1] = *(unsigned*)&smh[(wm + lr + 8) * 72 + k];
        qf[ks][2] = *(unsigned*)&smh[(wm + lr) * 72 + k + 8];
        qf[ks][3] = *(unsigned*)&smh[(wm + lr + 8) * 72 + k + 8];
    }
    __syncthreads();

#define AISSUE(kt)                                                         \
    do {                                                                   \
        const unsigned so_ = (unsigned)((kt) % 3) * ATT_STG_B;             \
        const __half* kg_ = Kp + (size_t)((kt) * 128 + tr) * Dd + tc;      \
        const __half* vg_ = Vp + (size_t)((kt) * 128 + tr) * Dd + tc;      \
        _Pragma("unroll")                                                  \
        for (int i_ = 0; i_ < 4; i_++) {                                   \
            cp16(k_st + so_ + i_ * 32 * 144, kg_ + (size_t)(32 * i_) * Dd);\
            cp16(v_st + so_ + i_ * 32 * 144, vg_ + (size_t)(32 * i_) * Dd);\
        }                                                                  \
        if (t < 32)                                                        \
            cp16(sbase + ATT_D_OFF + ((kt) % 3) * 512 + t * 16,            \
                 g_D + (size_t)bh * Ls + (kt) * 128 + t * 4);              \
        cp_commit();                                                       \
    } while (0)

    AISSUE(0);
    if (it >= 1) AISSUE(1);

    float yacc[8][4];
#pragma unroll
    for (int i = 0; i < 8; i++)
#pragma unroll
        for (int q = 0; q < 4; q++) yacc[i][q] = 0.f;

    const int i0r = it * 128 + wm + lr;
    const int i1r = i0r + 8;

#pragma unroll 1
    for (int kt = 0; kt <= it; kt++) {
        const int s = kt % 3;
        const unsigned so = (unsigned)s * ATT_STG_B;
        if (kt == it) cp_wait<0>(); else cp_wait<1>();
        __syncthreads();   // single barrier: data of stage kt visible; stage (kt+2)%3 free
        if (kt + 2 <= it) AISSUE(kt + 2);
        const float* dsm = (const float*)((const char*)smh + ATT_D_OFF + s * 512);

        const bool diag = (kt == it);
#pragma unroll
        for (int ntp = 0; ntp < 8; ntp++) {
            float acc0[4] = {0.f, 0.f, 0.f, 0.f};
            float acc1[4] = {0.f, 0.f, 0.f, 0.f};
#pragma unroll
            for (int ks = 0; ks < 4; ks++) {
                unsigned bq[4];
                ldsm4(bq, kb0 + so + (ntp * 16 * 72 + ks * 16) * 2);
                mma16(acc0, qf[ks], &bq[0]);
                mma16(acc1, qf[ks], &bq[2]);
            }
            // hoist V fragments: overlap LDSM with the exp chain below
            unsigned bt[4][4];
#pragma unroll
            for (int dtp = 0; dtp < 4; dtp++)
                ldsm4t(bt[dtp], Vb0 + so + (ntp * 16 * 72 + dtp * 16) * 2);

            int jl0 = ntp * 16 + lc * 2;
            int jl1 = jl0 + 8;
            float d0 = dsm[jl0], d1 = dsm[jl0 + 1];
            float d2 = dsm[jl1], d3 = dsm[jl1 + 1];
            float w00 = ex2(fmaf(acc0[0], SC2, d0));
            float w01 = ex2(fmaf(acc0[1], SC2, d1));
            float w10 = ex2(fmaf(acc0[2], SC2, d0));
            float w11 = ex2(fmaf(acc0[3], SC2, d1));
            float w20 = ex2(fmaf(acc1[0], SC2, d2));
            float w21 = ex2(fmaf(acc1[1], SC2, d3));
            float w30 = ex2(fmaf(acc1[2], SC2, d2));
            float w31 = ex2(fmaf(acc1[3], SC2, d3));
            if (diag) {
                int jg0 = kt * 128 + jl0, jg1 = kt * 128 + jl1;
                if (i0r < jg0)     w00 = 0.f;
                if (i0r < jg0 + 1) w01 = 0.f;
                if (i1r < jg0)     w10 = 0.f;
                if (i1r < jg0 + 1) w11 = 0.f;
                if (i0r < jg1)     w20 = 0.f;
                if (i0r < jg1 + 1) w21 = 0.f;
                if (i1r < jg1)     w30 = 0.f;
                if (i1r < jg1 + 1) w31 = 0.f;
            }
            unsigned aw[4];
            aw[0] = pack2(w00, w01);
            aw[1] = pack2(w10, w11);
            aw[2] = pack2(w20, w21);
            aw[3] = pack2(w30, w31);
#pragma unroll
            for (int dtp = 0; dtp < 4; dtp++) {
                mma16(yacc[dtp * 2],     aw, &bt[dtp][0]);
                mma16(yacc[dtp * 2 + 1], aw, &bt[dtp][2]);
            }
        }
    }
#undef AISSUE

#pragma unroll
    for (int dt = 0; dt < 8; dt++) {
        int d0 = dt * 8 + lc * 2;
        *(__half2*)&g_Y[((size_t)(b * Ls + i0r)) * Cc + h * Dd + d0] =
            __floats2half2_rn(yacc[dt][0], yacc[dt][1]);
        *(__half2*)&g_Y[((size_t)(b * Ls + i1r)) * Cc + h * Dd + d0] =
            __floats2half2_rn(yacc[dt][2], yacc[dt][3]);
    }
}

// ---------------------------------------------------------------------------
// Launch
// ---------------------------------------------------------------------------
extern "C" void kernel_launch(void* const* d_in, const int* in_sizes, int n_in,
                              void* d_out, int out_size) {
    const float* x     = (const float*)d_in[0];
    const float* Wqkv  = (const float*)d_in[1];
    const float* bqkv  = (const float*)d_in[2];
    const float* Wproj = (const float*)d_in[3];
    const float* bproj = (const float*)d_in[4];
    float* out = (float*)d_out;

    __half *xh, *wq, *wp, *yh;
    cudaGetSymbolAddress((void**)&xh, g_Xh);
    cudaGetSymbolAddress((void**)&wq, g_Wqkvh);
    cudaGetSymbolAddress((void**)&wp, g_Wprojh);
    cudaGetSymbolAddress((void**)&yh, g_Y);

    (void)cudaFuncSetAttribute(gemm_big<NQKV, 1>,
                               cudaFuncAttributeMaxDynamicSharedMemorySize, GB_SMEM);
    (void)cudaFuncSetAttribute(gemm_big<Cc, 0>,
                               cudaFuncAttributeMaxDynamicSharedMemorySize, GB_SMEM);
    (void)cudaFuncSetAttribute(stats_kernel2,
                               cudaFuncAttributeMaxDynamicSharedMemorySize, ST_SMEM);
    (void)cudaFuncSetAttribute(attn_kernel2,
                               cudaFuncAttributeMaxDynamicSharedMemorySize, P2_SMEM);

    // pre-pass: all three fp32 -> half conversions in one launch
    conv_all_kernel<<<12288, 256>>>(x, Wqkv, Wproj);

    // QKV projection, scatter half into per-head Q/K/V
    gemm_big<NQKV, 1><<<dim3(MT / 128, NQKV / 256), 256, GB_SMEM>>>(xh, wq, bqkv, nullptr);
    // softmax stats + fused attention
    stats_kernel2<<<dim3(8, BHn), 256, ST_SMEM>>>();
    attn_kernel2<<<dim3(8, BHn), 256, P2_SMEM>>>();
    // output projection (fp32 out)
    gemm_big<Cc, 0><<<dim3(MT / 128, Cc / 256), 256, GB_SMEM>>>(yh, wp, bproj, out);
}